// round 2
// baseline (speedup 1.0000x reference)
#include <cuda_runtime.h>
#include <cstdint>

// Problem constants (fixed shapes for KANLayer_17265768530645)
#define B_SZ    8192
#define D_IN    512
#define D_OUT   128
#define KK      16
#define X_MIN_F (-3.0f)
// X_MAX - X_MIN + EPS = 6 + 1e-8
#define DENOM   6.00000001f
#define SCALE_F (15.0f / DENOM)     // pos = (x - X_MIN) * SCALE
#define H_F     (DENOM / 15.0f)     // grid step in x units

// Fused table: [i][k][0:128] = w0' rows, [i][k][128:256] = wd' rows  (8 MB)
__device__ float g_tab[D_IN * KK * 2 * D_OUT];
// Transposed skip weights for rare out-of-range correction: [i][o] (256 KB)
__device__ float g_st[D_IN * D_OUT];

// ---------------------------------------------------------------------------
// Prep: transpose + fold skip into the interpolation table.
// grid = 512 (one CTA per i), block = 128 threads.
// ---------------------------------------------------------------------------
__global__ void kan_prep(const float* __restrict__ w,   // (128, 512, 16)
                         const float* __restrict__ s)   // (128, 512)
{
    const int i = blockIdx.x;
    const int t = threadIdx.x;
    __shared__ float ws[D_OUT][KK + 1];  // pad to kill bank conflicts
    __shared__ float ss[D_OUT];

    // Load w[:, i, :] (2048 floats). Consecutive threads read contiguous k.
    #pragma unroll
    for (int r = 0; r < 16; r++) {
        int idx = r * 128 + t;          // 0..2047
        int o = idx >> 4;
        int k = idx & 15;
        ws[o][k] = w[(size_t)o * (D_IN * KK) + i * KK + k];
    }
    ss[t] = s[(size_t)t * D_IN + i];
    __syncthreads();

    const int o = t;
    const float so = ss[o];
    g_st[i * D_OUT + o] = so;
    float* base = g_tab + (size_t)i * (KK * 2 * D_OUT);
    #pragma unroll
    for (int k = 0; k < KK; k++) {
        float w0 = ws[o][k];
        float w1 = (k < KK - 1) ? ws[o][k + 1] : w0;
        // fold skip: + (X_MIN + k*h) * s   and   + h * s
        base[k * 256 + o]       = w0 + fmaf((float)k, H_F, X_MIN_F) * so;
        base[k * 256 + 128 + o] = (w1 - w0) + H_F * so;
    }
}

// ---------------------------------------------------------------------------
// Main: one warp handles 4 batch rows across all 128 outputs.
// lane owns outputs [4*lane, 4*lane+4). Row gathers are one coalesced
// 512B LDG.128 per row. Skip is pre-folded; rare clipped-x correction branch.
// grid = 256 CTAs x 256 threads -> 2048 warps -> 8192 b rows.
// ---------------------------------------------------------------------------
__device__ __forceinline__ void kan_proc(float4& acc, float xx,
                                         const float* __restrict__ tb,
                                         const float* __restrict__ st,
                                         int lane)
{
    float posr = (xx - X_MIN_F) * SCALE_F;
    float pos  = fminf(fmaxf(posr, 0.0f), 15.0f);
    float fl   = floorf(pos);
    float f    = pos - fl;
    int   idx  = (int)fl;

    const float4* p = reinterpret_cast<const float4*>(tb + (idx << 8)) + lane;
    float4 r0 = p[0];    // w0' row chunk
    float4 rd = p[32];   // wd' row chunk (+512 B)

    acc.x += fmaf(f, rd.x, r0.x);
    acc.y += fmaf(f, rd.y, r0.y);
    acc.z += fmaf(f, rd.z, r0.z);
    acc.w += fmaf(f, rd.w, r0.w);

    // Rare (|x| > 3): skip term used clipped x-hat; add (x - x_hat) * s row.
    if (posr != pos) {
        float ex = xx - fmaf(pos, H_F, X_MIN_F);
        float4 sv = reinterpret_cast<const float4*>(st)[lane];
        acc.x = fmaf(ex, sv.x, acc.x);
        acc.y = fmaf(ex, sv.y, acc.y);
        acc.z = fmaf(ex, sv.z, acc.z);
        acc.w = fmaf(ex, sv.w, acc.w);
    }
}

__global__ __launch_bounds__(256)
void kan_main(const float* __restrict__ x,
              const float* __restrict__ bias,
              float* __restrict__ y)
{
    const int warp = (blockIdx.x * 256 + threadIdx.x) >> 5;  // 0..2047
    const int lane = threadIdx.x & 31;
    const int b0   = warp * 4;
    const int o4   = lane * 4;

    const float4 bi = *reinterpret_cast<const float4*>(bias + o4);
    float4 a0 = bi, a1 = bi, a2 = bi, a3 = bi;

    const float* xr = x + (size_t)b0 * D_IN;

    for (int i4 = 0; i4 < D_IN; i4 += 4) {
        float4 x0 = *reinterpret_cast<const float4*>(xr + i4);
        float4 x1 = *reinterpret_cast<const float4*>(xr + D_IN + i4);
        float4 x2 = *reinterpret_cast<const float4*>(xr + 2 * D_IN + i4);
        float4 x3 = *reinterpret_cast<const float4*>(xr + 3 * D_IN + i4);
        #pragma unroll
        for (int ii = 0; ii < 4; ii++) {
            const int i = i4 + ii;
            const float* tb = g_tab + (size_t)i * 4096;
            const float* st = g_st + i * D_OUT;
            float xa = (ii == 0) ? x0.x : (ii == 1) ? x0.y : (ii == 2) ? x0.z : x0.w;
            float xb = (ii == 0) ? x1.x : (ii == 1) ? x1.y : (ii == 2) ? x1.z : x1.w;
            float xc = (ii == 0) ? x2.x : (ii == 1) ? x2.y : (ii == 2) ? x2.z : x2.w;
            float xd = (ii == 0) ? x3.x : (ii == 1) ? x3.y : (ii == 2) ? x3.z : x3.w;
            kan_proc(a0, xa, tb, st, lane);
            kan_proc(a1, xb, tb, st, lane);
            kan_proc(a2, xc, tb, st, lane);
            kan_proc(a3, xd, tb, st, lane);
        }
    }

    float* yp = y + (size_t)b0 * D_OUT + o4;
    *reinterpret_cast<float4*>(yp)             = a0;
    *reinterpret_cast<float4*>(yp + D_OUT)     = a1;
    *reinterpret_cast<float4*>(yp + 2 * D_OUT) = a2;
    *reinterpret_cast<float4*>(yp + 3 * D_OUT) = a3;
}

// ---------------------------------------------------------------------------
// kernel_launch: inputs per metadata order: x, weights, skip_w, bias
// ---------------------------------------------------------------------------
extern "C" void kernel_launch(void* const* d_in, const int* in_sizes, int n_in,
                              void* d_out, int out_size)
{
    const float* x    = (const float*)d_in[0];
    const float* w    = (const float*)d_in[1];
    const float* skip = (const float*)d_in[2];
    const float* bias = (const float*)d_in[3];
    float* y = (float*)d_out;

    kan_prep<<<D_IN, 128>>>(w, skip);
    // 8192 b / 4 per warp = 2048 warps; 8 warps per CTA -> 256 CTAs
    kan_main<<<256, 256>>>(x, bias, y);
}

// round 3
// speedup vs baseline: 1.1756x; 1.1756x over previous
#include <cuda_runtime.h>
#include <cuda_fp16.h>
#include <cstdint>

// Problem constants (fixed shapes for KANLayer_17265768530645)
#define B_SZ    8192
#define D_IN    512
#define D_OUT   128
#define KK      16
#define X_MIN_F (-3.0f)
#define DENOM   6.00000001f           // X_MAX - X_MIN + EPS
#define SCALE_F (15.0f / DENOM)       // pos = (x - X_MIN) * SCALE
#define H_F     (DENOM / 15.0f)       // grid step in x units

// fp16 fused table: per (i,k) one 512B row of 256 halves.
// Row layout: 32 lane-groups g, each 8 halves:
//   [w0'[4g], w0'[4g+1], w0'[4g+2], w0'[4g+3], wd'[4g], wd'[4g+1], wd'[4g+2], wd'[4g+3]]
// w0'[o] = w[o,i,k] + (X_MIN + k*h)*s[o,i]   (skip folded, fp32 math, fp16 store)
// wd'[o] = (w[o,i,k+1]-w[o,i,k]) + h*s[o,i]  (0 diff at k=15)
__device__ __half g_tab[(size_t)D_IN * KK * 2 * D_OUT];   // 4 MB
// fp32 transposed skip for rare |x|>3 correction: [i][o]
__device__ float  g_st[D_IN * D_OUT];                      // 256 KB

// ---------------------------------------------------------------------------
// Prep: transpose + fold skip + quantize to fp16. grid=512 (one CTA per i).
// ---------------------------------------------------------------------------
__global__ void kan_prep(const float* __restrict__ w,   // (128, 512, 16)
                         const float* __restrict__ s)   // (128, 512)
{
    const int i = blockIdx.x;
    const int o = threadIdx.x;   // 0..127

    float wv[KK];
    #pragma unroll
    for (int k = 0; k < KK; k++)
        wv[k] = w[(size_t)o * (D_IN * KK) + i * KK + k];
    const float so = s[(size_t)o * D_IN + i];
    g_st[i * D_OUT + o] = so;

    const int g = o >> 2, j = o & 3;
    __half* base = g_tab + (size_t)i * (KK * 2 * D_OUT);
    #pragma unroll
    for (int k = 0; k < KK; k++) {
        float w0 = wv[k];
        float w1 = (k < KK - 1) ? wv[k + 1] : w0;
        float w0f = w0 + fmaf((float)k, H_F, X_MIN_F) * so;
        float wdf = (w1 - w0) + H_F * so;
        __half* row = base + k * 256 + g * 8;
        row[j]     = __float2half_rn(w0f);
        row[4 + j] = __float2half_rn(wdf);
    }
}

// ---------------------------------------------------------------------------
// Main: one warp per batch row. Lane owns outputs [4*lane, 4*lane+4).
// One LDG.128 per (b,i): fp16 (w0',wd') packed row chunk. HFMA2 lerp,
// fp32 accumulate. grid = 1024 CTAs x 256 threads = 8192 warps.
// ---------------------------------------------------------------------------
__device__ __forceinline__ void kan_proc(float& a0, float& a1, float& a2, float& a3,
                                         float xx,
                                         const uint4* __restrict__ tb_u4,
                                         const float* __restrict__ st,
                                         int lane)
{
    float posr = (xx - X_MIN_F) * SCALE_F;
    float pos  = fminf(fmaxf(posr, 0.0f), 15.0f);
    int   idx  = (int)pos;               // trunc (pos >= 0)
    float f    = pos - (float)idx;

    uint4 v = tb_u4[(idx << 5) + lane];  // 32 uint4 per (i,k) row

    __half2 f2   = __float2half2_rn(f);
    __half2 w001 = *reinterpret_cast<__half2*>(&v.x);
    __half2 w023 = *reinterpret_cast<__half2*>(&v.y);
    __half2 wd01 = *reinterpret_cast<__half2*>(&v.z);
    __half2 wd23 = *reinterpret_cast<__half2*>(&v.w);

    float2 t01 = __half22float2(__hfma2(f2, wd01, w001));
    float2 t23 = __half22float2(__hfma2(f2, wd23, w023));
    a0 += t01.x;  a1 += t01.y;  a2 += t23.x;  a3 += t23.y;

    // Rare (|x| > 3): folded skip used clipped x-hat; add (x - x_hat)*s in fp32.
    if (__builtin_expect(posr != pos, 0)) {
        float ex = xx - fmaf(pos, H_F, X_MIN_F);
        float4 sv = reinterpret_cast<const float4*>(st)[lane];
        a0 = fmaf(ex, sv.x, a0);
        a1 = fmaf(ex, sv.y, a1);
        a2 = fmaf(ex, sv.z, a2);
        a3 = fmaf(ex, sv.w, a3);
    }
}

__global__ __launch_bounds__(256)
void kan_main(const float* __restrict__ x,
              const float* __restrict__ bias,
              float* __restrict__ y)
{
    const int b    = (blockIdx.x * 256 + threadIdx.x) >> 5;  // 0..8191
    const int lane = threadIdx.x & 31;

    const float4 bi = *reinterpret_cast<const float4*>(bias + lane * 4);
    float a0 = bi.x, a1 = bi.y, a2 = bi.z, a3 = bi.w;

    const float* xr = x + (size_t)b * D_IN;

    for (int i4 = 0; i4 < D_IN; i4 += 4) {
        float4 xv = *reinterpret_cast<const float4*>(xr + i4);  // warp-broadcast
        const uint4* tb0 = reinterpret_cast<const uint4*>(g_tab) + (size_t)i4 * 512;
        const float* st0 = g_st + i4 * D_OUT;
        kan_proc(a0, a1, a2, a3, xv.x, tb0,        st0,           lane);
        kan_proc(a0, a1, a2, a3, xv.y, tb0 + 512,  st0 + 128,     lane);
        kan_proc(a0, a1, a2, a3, xv.z, tb0 + 1024, st0 + 256,     lane);
        kan_proc(a0, a1, a2, a3, xv.w, tb0 + 1536, st0 + 384,     lane);
    }

    float4 out = make_float4(a0, a1, a2, a3);
    *reinterpret_cast<float4*>(y + (size_t)b * D_OUT + lane * 4) = out;
}

// ---------------------------------------------------------------------------
// kernel_launch: inputs per metadata order: x, weights, skip_w, bias
// ---------------------------------------------------------------------------
extern "C" void kernel_launch(void* const* d_in, const int* in_sizes, int n_in,
                              void* d_out, int out_size)
{
    const float* x    = (const float*)d_in[0];
    const float* w    = (const float*)d_in[1];
    const float* skip = (const float*)d_in[2];
    const float* bias = (const float*)d_in[3];
    float* y = (float*)d_out;

    kan_prep<<<D_IN, 128>>>(w, skip);
    kan_main<<<B_SZ / 8, 256>>>(x, bias, y);
}

// round 4
// speedup vs baseline: 1.4506x; 1.2339x over previous
#include <cuda_runtime.h>
#include <cuda_fp16.h>
#include <cstdint>

// Problem constants (fixed shapes for KANLayer_17265768530645)
#define B_SZ    8192
#define D_IN    512
#define D_OUT   128
#define KK      16
#define X_MIN_F (-3.0f)
#define DENOM   6.00000001f           // X_MAX - X_MIN + EPS
#define SCALE_F (15.0f / DENOM)       // posr = (x - X_MIN) * SCALE
#define H_F     (DENOM / 15.0f)       // grid step in x units

// Per-i block: 17 rows x 512 B. Rows 0..15: {w0'(k), wd'(k)}; row 16: low-clip
// row {w0'(0), h*s} so f=posr(<0) reproduces w[0] + x*s exactly.
// Row layout: 32 lane-groups g of 8 halves: [w0[4g..4g+3], wd[4g..4g+3]].
#define ROWS_I   17
#define ROW_B    512                   // bytes per row
#define I_STRIDE (ROWS_I * ROW_B)      // 8704 bytes per i

__device__ __half    g_tab[(size_t)D_IN * ROWS_I * 256];   // ~4.5 MB
__device__ uint32_t  g_enc[(size_t)B_SZ * D_IN];           // 16 MB

// ---------------------------------------------------------------------------
// Prep: transpose + fold skip + fp16 quantize + clip rows. grid=512, block=128.
// ---------------------------------------------------------------------------
__global__ void kan_prep(const float* __restrict__ w,   // (128, 512, 16)
                         const float* __restrict__ s)   // (128, 512)
{
    const int i = blockIdx.x;
    const int o = threadIdx.x;   // 0..127

    float wv[KK];
    #pragma unroll
    for (int k = 0; k < KK; k++)
        wv[k] = w[(size_t)o * (D_IN * KK) + i * KK + k];
    const float so = s[(size_t)o * D_IN + i];

    const int g = o >> 2, j = o & 3;
    __half* base = g_tab + (size_t)i * (ROWS_I * 256);
    #pragma unroll
    for (int k = 0; k < KK; k++) {
        float w0 = wv[k];
        float w1 = (k < KK - 1) ? wv[k + 1] : w0;
        float w0f = w0 + fmaf((float)k, H_F, X_MIN_F) * so;  // + x_hat(k)*s
        float wdf = (w1 - w0) + H_F * so;
        __half* row = base + k * 256 + g * 8;
        row[j]     = __float2half_rn(w0f);
        row[4 + j] = __float2half_rn(wdf);
    }
    // Row 16: low-clip. w0 = w[0] + X_MIN*s, wd = h*s; with f = posr (< 0):
    // w0 + f*wd = w[0] + x*s  (exact skip for x < X_MIN).
    {
        __half* row = base + 16 * 256 + g * 8;
        row[j]     = __float2half_rn(wv[0] + X_MIN_F * so);
        row[4 + j] = __float2half_rn(H_F * so);
    }
}

// ---------------------------------------------------------------------------
// Encode pass: per (b,i) pack {f as fp16, row byte-offset} into one uint32.
// ---------------------------------------------------------------------------
__device__ __forceinline__ uint32_t enc1(float xx)
{
    float posr = (xx - X_MIN_F) * SCALE_F;
    int idx; float f;
    if (posr < 0.0f) { idx = 16; f = posr; }               // low clip (exact)
    else {
        float p = fminf(posr, 15.0f);
        idx = (int)p;                                      // floor (p >= 0)
        f = posr - (float)idx;                             // high clip: f>1 ok (exact)
    }
    __half h = __float2half_rn(f);
    return ((uint32_t)__half_as_ushort(h) << 16) | ((uint32_t)idx * ROW_B);
}

__global__ __launch_bounds__(256)
void kan_encode(const float* __restrict__ x)   // (B, 512)
{
    int t = blockIdx.x * 256 + threadIdx.x;    // over B*D_IN/4
    float4 xv = reinterpret_cast<const float4*>(x)[t];
    uint4 e;
    e.x = enc1(xv.x);
    e.y = enc1(xv.y);
    e.z = enc1(xv.z);
    e.w = enc1(xv.w);
    reinterpret_cast<uint4*>(g_enc)[t] = e;
}

// ---------------------------------------------------------------------------
// Main: one warp per batch row; lane owns outputs [4*lane, 4*lane+4).
// Per (b,i): AND + IMAD.WIDE + PRMT + LDG.128 + 2 HFMA2 + 4 F2F + 4 FADD.
// ---------------------------------------------------------------------------
__device__ __forceinline__ void kan_proc(float& a0, float& a1, float& a2, float& a3,
                                         uint32_t e, const char* __restrict__ bb)
{
    const uint4 v = *reinterpret_cast<const uint4*>(bb + (e & 0xFFFFu));
    uint32_t f2b = __byte_perm(e, e, 0x3232);              // {f,f} half2
    __half2 f2   = *reinterpret_cast<__half2*>(&f2b);

    __half2 w001 = *reinterpret_cast<const __half2*>(&v.x);
    __half2 w023 = *reinterpret_cast<const __half2*>(&v.y);
    __half2 wd01 = *reinterpret_cast<const __half2*>(&v.z);
    __half2 wd23 = *reinterpret_cast<const __half2*>(&v.w);

    float2 t01 = __half22float2(__hfma2(f2, wd01, w001));
    float2 t23 = __half22float2(__hfma2(f2, wd23, w023));
    a0 += t01.x;  a1 += t01.y;  a2 += t23.x;  a3 += t23.y;
}

__global__ __launch_bounds__(256)
void kan_main(const float* __restrict__ bias,
              float* __restrict__ y)
{
    const int b    = (blockIdx.x * 256 + threadIdx.x) >> 5;  // 0..8191
    const int lane = threadIdx.x & 31;

    const float4 bi = reinterpret_cast<const float4*>(bias)[lane];
    float a0 = bi.x, a1 = bi.y, a2 = bi.z, a3 = bi.w;

    const uint4* ep = reinterpret_cast<const uint4*>(g_enc) + (size_t)b * (D_IN / 4);
    const char*  bb = reinterpret_cast<const char*>(g_tab) + lane * 16;

    #pragma unroll 4
    for (int i4 = 0; i4 < D_IN / 4; i4++) {
        uint4 e = ep[i4];                      // warp-broadcast, L1
        kan_proc(a0, a1, a2, a3, e.x, bb);
        kan_proc(a0, a1, a2, a3, e.y, bb + I_STRIDE);
        kan_proc(a0, a1, a2, a3, e.z, bb + 2 * I_STRIDE);
        kan_proc(a0, a1, a2, a3, e.w, bb + 3 * I_STRIDE);
        bb += 4 * I_STRIDE;
    }

    float4 out = make_float4(a0, a1, a2, a3);
    reinterpret_cast<float4*>(y + (size_t)b * D_OUT)[lane] = out;
}

// ---------------------------------------------------------------------------
// kernel_launch: inputs per metadata order: x, weights, skip_w, bias
// ---------------------------------------------------------------------------
extern "C" void kernel_launch(void* const* d_in, const int* in_sizes, int n_in,
                              void* d_out, int out_size)
{
    const float* x    = (const float*)d_in[0];
    const float* w    = (const float*)d_in[1];
    const float* skip = (const float*)d_in[2];
    const float* bias = (const float*)d_in[3];
    float* y = (float*)d_out;

    kan_prep<<<D_IN, 128>>>(w, skip);
    kan_encode<<<(B_SZ * D_IN / 4) / 256, 256>>>(x);
    kan_main<<<B_SZ / 8, 256>>>(bias, y);
}

// round 5
// speedup vs baseline: 1.5278x; 1.0532x over previous
#include <cuda_runtime.h>
#include <cuda_fp16.h>
#include <cstdint>

// Problem constants (fixed shapes for KANLayer_17265768530645)
#define B_SZ    8192
#define D_IN    512
#define D_OUT   128
#define KK      16
#define X_MIN_F (-3.0f)
#define DENOM   6.00000001f           // X_MAX - X_MIN + EPS
#define SCALE_F (15.0f / DENOM)       // posr = (x - X_MIN) * SCALE
#define H_F     (DENOM / 15.0f)       // grid step in x units

// Per-i block: 17 rows x 512 B. Rows 0..15: {w0'(k), wd'(k)}; row 16: low-clip
// row {w0'(0), h*s} so f=posr(<0) reproduces w[0] + x*s exactly.
// Row layout: 32 lane-groups g of 8 halves: [w0[4g..4g+3], wd[4g..4g+3]].
#define ROWS_I   17
#define ROW_B    512                   // bytes per row
#define I_STRIDE (ROWS_I * ROW_B)      // 8704 bytes per i

__device__ __align__(16) __half    g_tab[(size_t)D_IN * ROWS_I * 256];  // ~4.5 MB
__device__ __align__(16) uint32_t  g_enc[(size_t)B_SZ * D_IN];          // 16 MB

// ---------------------------------------------------------------------------
// Prep: transpose + fold skip + fp16 quantize + clip rows. grid=512, block=128.
// ---------------------------------------------------------------------------
__global__ void kan_prep(const float* __restrict__ w,   // (128, 512, 16)
                         const float* __restrict__ s)   // (128, 512)
{
    const int i = blockIdx.x;
    const int o = threadIdx.x;   // 0..127

    float wv[KK];
    #pragma unroll
    for (int k = 0; k < KK; k++)
        wv[k] = w[(size_t)o * (D_IN * KK) + i * KK + k];
    const float so = s[(size_t)o * D_IN + i];

    const int g = o >> 2, j = o & 3;
    __half* base = g_tab + (size_t)i * (ROWS_I * 256);
    #pragma unroll
    for (int k = 0; k < KK; k++) {
        float w0 = wv[k];
        float w1 = (k < KK - 1) ? wv[k + 1] : w0;
        float w0f = w0 + fmaf((float)k, H_F, X_MIN_F) * so;  // + x_hat(k)*s
        float wdf = (w1 - w0) + H_F * so;
        __half* row = base + k * 256 + g * 8;
        row[j]     = __float2half_rn(w0f);
        row[4 + j] = __float2half_rn(wdf);
    }
    // Row 16: low-clip. w0 = w[0] + X_MIN*s, wd = h*s; f = posr (< 0) gives
    // w[0] + x*s exactly.
    {
        __half* row = base + 16 * 256 + g * 8;
        row[j]     = __float2half_rn(wv[0] + X_MIN_F * so);
        row[4 + j] = __float2half_rn(H_F * so);
    }
}

// ---------------------------------------------------------------------------
// Encode pass: per (b,i) pack {f as fp16, row byte-offset} into one uint32.
// ---------------------------------------------------------------------------
__device__ __forceinline__ uint32_t enc1(float xx)
{
    float posr = (xx - X_MIN_F) * SCALE_F;
    int idx; float f;
    if (posr < 0.0f) { idx = 16; f = posr; }               // low clip (exact)
    else {
        float p = fminf(posr, 15.0f);
        idx = (int)p;                                      // floor (p >= 0)
        f = posr - (float)idx;                             // high clip: f>1 ok (exact)
    }
    __half h = __float2half_rn(f);
    return ((uint32_t)__half_as_ushort(h) << 16) | ((uint32_t)idx * ROW_B);
}

__global__ __launch_bounds__(256)
void kan_encode(const float* __restrict__ x)   // (B, 512)
{
    int t = blockIdx.x * 256 + threadIdx.x;    // over B*D_IN/4
    float4 xv = reinterpret_cast<const float4*>(x)[t];
    uint4 e;
    e.x = enc1(xv.x);
    e.y = enc1(xv.y);
    e.z = enc1(xv.z);
    e.w = enc1(xv.w);
    reinterpret_cast<uint4*>(g_enc)[t] = e;
}

// ---------------------------------------------------------------------------
// Main: one warp per batch row; lane owns outputs [4*lane, 4*lane+4).
// fp16 pair-accumulation, packed f32x2 flush every 2 iterations.
// ---------------------------------------------------------------------------
__device__ __forceinline__ void kan_one(uint32_t e, const char* __restrict__ bb,
                                        __half2& h01, __half2& h23)
{
    const uint4 v = *reinterpret_cast<const uint4*>(bb + (e & 0xFFFFu));
    uint32_t f2b = __byte_perm(e, e, 0x3232);              // {f,f} half2
    __half2 f2   = *reinterpret_cast<const __half2*>(&f2b);

    h01 = __hfma2(f2, *reinterpret_cast<const __half2*>(&v.z),
                      *reinterpret_cast<const __half2*>(&v.x));
    h23 = __hfma2(f2, *reinterpret_cast<const __half2*>(&v.w),
                      *reinterpret_cast<const __half2*>(&v.y));
}

__device__ __forceinline__ void kan_pair(uint32_t ea, uint32_t eb,
                                         const char* __restrict__ bb,
                                         unsigned long long& acc01,
                                         unsigned long long& acc23)
{
    __half2 a01, a23, b01, b23;
    kan_one(ea, bb, a01, a23);
    kan_one(eb, bb + I_STRIDE, b01, b23);
    __half2 s01 = __hadd2(a01, b01);
    __half2 s23 = __hadd2(a23, b23);
    float2 f01 = __half22float2(s01);
    float2 f23 = __half22float2(s23);
    unsigned long long p01, p23;
    asm("mov.b64 %0, {%1, %2};" : "=l"(p01) : "f"(f01.x), "f"(f01.y));
    asm("mov.b64 %0, {%1, %2};" : "=l"(p23) : "f"(f23.x), "f"(f23.y));
    asm("add.rn.f32x2 %0, %0, %1;" : "+l"(acc01) : "l"(p01));
    asm("add.rn.f32x2 %0, %0, %1;" : "+l"(acc23) : "l"(p23));
}

__global__ __launch_bounds__(256)
void kan_main(const float* __restrict__ bias,
              float* __restrict__ y)
{
    const int b    = (blockIdx.x * 256 + threadIdx.x) >> 5;  // 0..8191
    const int lane = threadIdx.x & 31;

    const float4 bi = reinterpret_cast<const float4*>(bias)[lane];
    unsigned long long acc01, acc23;
    asm("mov.b64 %0, {%1, %2};" : "=l"(acc01) : "f"(bi.x), "f"(bi.y));
    asm("mov.b64 %0, {%1, %2};" : "=l"(acc23) : "f"(bi.z), "f"(bi.w));

    const uint4* ep = reinterpret_cast<const uint4*>(g_enc) + (size_t)b * (D_IN / 4);
    const char*  bb = reinterpret_cast<const char*>(g_tab) + lane * 16;

    #pragma unroll 2
    for (int i4 = 0; i4 < D_IN / 4; i4++) {
        uint4 e = ep[i4];                      // warp-broadcast, L1
        kan_pair(e.x, e.y, bb,                acc01, acc23);
        kan_pair(e.z, e.w, bb + 2 * I_STRIDE, acc01, acc23);
        bb += 4 * I_STRIDE;
    }

    float4 out;
    asm("mov.b64 {%0, %1}, %2;" : "=f"(out.x), "=f"(out.y) : "l"(acc01));
    asm("mov.b64 {%0, %1}, %2;" : "=f"(out.z), "=f"(out.w) : "l"(acc23));
    reinterpret_cast<float4*>(y + (size_t)b * D_OUT)[lane] = out;
}

// ---------------------------------------------------------------------------
// kernel_launch: inputs per metadata order: x, weights, skip_w, bias
// ---------------------------------------------------------------------------
extern "C" void kernel_launch(void* const* d_in, const int* in_sizes, int n_in,
                              void* d_out, int out_size)
{
    const float* x    = (const float*)d_in[0];
    const float* w    = (const float*)d_in[1];
    const float* skip = (const float*)d_in[2];
    const float* bias = (const float*)d_in[3];
    float* y = (float*)d_out;

    kan_prep<<<D_IN, 128>>>(w, skip);
    kan_encode<<<(B_SZ * D_IN / 4) / 256, 256>>>(x);
    kan_main<<<B_SZ / 8, 256>>>(bias, y);
}